// round 6
// baseline (speedup 1.0000x reference)
#include <cuda_runtime.h>
#include <cstdint>

#define NN 8192      // nodes
#define DF 128       // feature dim
#define NA 512       // anchors
#define KSEL 32      // k nearest
#define MARGINF 1.0f

// distance-kernel tiling
#define TA 32
#define TN 64
#define RA 4
#define RN 2
#define SROW 132     // padded smem row stride (words); conflict-free LDS.128

#define MAXCAND 2048
#define NGRP 32      // per-row tile-min groups (tile index & 31)

// scratch (device globals: allocation-free)
__device__ __align__(16) float g_dist[2][NA][NN];    // full distance matrices (32 MB)
// complement-encoded row/group minima: stored c = ~bits(min). Zero-init decodes
// to 0xFFFFFFFF (+huge), k_topk resets to 0 after use -> identical every replay.
__device__ unsigned g_nmin[2][NA][NGRP];
__device__ float g_rowLoss[2 * NA];
__device__ unsigned int g_done;

// ---------------------------------------------------------------------------
// Kernel A: L1 distance matrix + per-tile row minima (prune bound producer).
// ---------------------------------------------------------------------------
__global__ __launch_bounds__(256) void k_dist(const float* __restrict__ out1,
                                              const float* __restrict__ out2,
                                              const int* __restrict__ an1,
                                              const int* __restrict__ an2) {
    extern __shared__ float sm[];
    float* sA = sm;                 // TA rows, stride SROW
    float* sN = sm + TA * SROW;     // TN rows, stride SROW

    const int side = blockIdx.z;
    const int aT = blockIdx.y;
    const int nT = blockIdx.x;
    const float* __restrict__ abase = side ? out2 : out1;
    const int* __restrict__ aidx = side ? an2 : an1;
    const float* __restrict__ nodes = side ? out1 : out2;
    const int tid = threadIdx.x;

    if (blockIdx.x == 0 && blockIdx.y == 0 && blockIdx.z == 0 && tid == 0) g_done = 0u;

    // stage anchor tile: gather 32 anchor rows
    for (int i = tid; i < TA * (DF / 4); i += 256) {
        int r = i >> 5, c = i & 31;
        int node = aidx[aT * TA + r];
        *(float4*)&sA[r * SROW + c * 4] =
            *(const float4*)&abase[(size_t)node * DF + c * 4];
    }
    // stage node tile
    const float4* nsrc = (const float4*)(nodes + (size_t)nT * TN * DF);
    for (int i = tid; i < TN * (DF / 4); i += 256) {
        int r = i >> 5, c = i & 31;
        *(float4*)&sN[r * SROW + c * 4] = nsrc[i];
    }
    __syncthreads();

    const int ta = tid >> 5;
    const int tn = tid & 31;
    float acc[RA][RN];
#pragma unroll
    for (int i = 0; i < RA; i++)
#pragma unroll
        for (int j = 0; j < RN; j++) acc[i][j] = 0.f;

    const float* aB = &sA[(ta * RA) * SROW];
    const float* nB = &sN[tn * SROW];

#pragma unroll 2
    for (int k = 0; k < DF; k += 4) {
        float4 av[RA], nv[RN];
#pragma unroll
        for (int i = 0; i < RA; i++) av[i] = *(const float4*)&aB[i * SROW + k];
#pragma unroll
        for (int j = 0; j < RN; j++) nv[j] = *(const float4*)&nB[j * 32 * SROW + k];
#pragma unroll
        for (int i = 0; i < RA; i++)
#pragma unroll
            for (int j = 0; j < RN; j++) {
                float s = acc[i][j];
                s += fabsf(av[i].x - nv[j].x);
                s += fabsf(av[i].y - nv[j].y);
                s += fabsf(av[i].z - nv[j].z);
                s += fabsf(av[i].w - nv[j].w);
                acc[i][j] = s;
            }
    }

    const int grp = nT & (NGRP - 1);
#pragma unroll
    for (int i = 0; i < RA; i++) {
        int A = aT * TA + ta * RA + i;
#pragma unroll
        for (int j = 0; j < RN; j++) {
            int n = nT * TN + tn + j * 32;
            g_dist[side][A][n] = acc[i][j];
        }
        // tile-row min -> complement-encoded global atomicMax (no return use)
        float m = fminf(acc[i][0], acc[i][1]);
#pragma unroll
        for (int o = 16; o; o >>= 1) m = fminf(m, __shfl_xor_sync(0xffffffffu, m, o));
        if (tn == 0) atomicMax(&g_nmin[side][A][grp], ~__float_as_uint(m));
    }
}

// ---------------------------------------------------------------------------
// Kernel B: per-row exact 32-smallest + relu-margin loss.
//   T0 = max over the 32 precomputed group minima (valid upper bound on the
//   32nd smallest). ONE pass over the row gathers {v <= T0}; 4x 8-bit radix
//   select finds the exact 32nd smallest T and L = #{v < T}; then
//   loss = sum_{v<T} relu(D-v) + (32-L)*relu(D-T).   Deterministic.
//   Last block (ticket) does the final reduction.
// ---------------------------------------------------------------------------
__global__ __launch_bounds__(256) void k_topk(const float* __restrict__ out1,
                                              const float* __restrict__ out2,
                                              const int* __restrict__ an1,
                                              const int* __restrict__ an2,
                                              float* __restrict__ outp) {
    const int row = blockIdx.x;                 // 0..1023
    const int side = row >> 9, a = row & (NA - 1);
    const float4* __restrict__ drow4 = (const float4*)&g_dist[side][a][0];
    const int tid = threadIdx.x;
    const int lane = tid & 31, wid = tid >> 5;

    __shared__ float sred[256];
    __shared__ float cand[MAXCAND];
    __shared__ unsigned hist[256];
    __shared__ unsigned wsum[8];
    __shared__ float wpart[8];
    __shared__ int scnt;
    __shared__ float T0s;
    __shared__ float Dsh;
    __shared__ unsigned selByte, selExc;
    __shared__ unsigned int ticket;

    // ---- T0 from precomputed group minima (warp 1), D[a] (warp-group 0) ----
    if (tid < DF) {
        int i1 = an1[a], i2 = an2[a];
        float part = fabsf(out1[(size_t)i1 * DF + tid] - out2[(size_t)i2 * DF + tid]);
        for (int o = 16; o; o >>= 1) part += __shfl_xor_sync(0xffffffffu, part, o);
        if (lane == 0) sred[wid] = part;
    }
    if (tid >= 224) {                            // warp 7: T0 + reset
        unsigned c = g_nmin[side][a][lane];
        g_nmin[side][a][lane] = 0u;              // reset for next replay
        float m = __uint_as_float(~c);
        for (int o = 16; o; o >>= 1) m = fmaxf(m, __shfl_xor_sync(0xffffffffu, m, o));
        if (lane == 0) T0s = m;
    }
    if (tid == 0) scnt = 0;
    __syncthreads();
    if (tid == 0) Dsh = sred[0] + sred[1] + sred[2] + sred[3] + MARGINF;
    const float T0 = T0s;

    // ---- single pass: gather candidates <= T0 ----
    for (int i = tid; i < NN / 4; i += 256) {
        float4 v = drow4[i];
        if (v.x <= T0) { int p = atomicAdd(&scnt, 1); if (p < MAXCAND) cand[p] = v.x; }
        if (v.y <= T0) { int p = atomicAdd(&scnt, 1); if (p < MAXCAND) cand[p] = v.y; }
        if (v.z <= T0) { int p = atomicAdd(&scnt, 1); if (p < MAXCAND) cand[p] = v.z; }
        if (v.w <= T0) { int p = atomicAdd(&scnt, 1); if (p < MAXCAND) cand[p] = v.w; }
    }
    __syncthreads();
    const int cnt = min(scnt, MAXCAND);

    // ---- radix select: exact 32nd smallest (positive floats: uint order) ----
    unsigned prefix = 0;
    unsigned target = KSEL;
    unsigned below = 0;
#pragma unroll
    for (int p = 3; p >= 0; --p) {
        const int shift = p * 8;
        hist[tid] = 0;
        __syncthreads();
        for (int i = tid; i < cnt; i += 256) {
            unsigned u = __float_as_uint(cand[i]);
            bool match = (p == 3) || ((u >> (shift + 8)) == (prefix >> (shift + 8)));
            if (match) atomicAdd(&hist[(u >> shift) & 0xFFu], 1u);
        }
        __syncthreads();
        unsigned h = hist[tid];
        unsigned inc = h;
#pragma unroll
        for (int o = 1; o < 32; o <<= 1) {
            unsigned n = __shfl_up_sync(0xffffffffu, inc, o);
            if (lane >= o) inc += n;
        }
        if (lane == 31) wsum[wid] = inc;
        __syncthreads();
        unsigned woff = 0;
        for (int w = 0; w < wid; w++) woff += wsum[w];
        inc += woff;
        unsigned exc = inc - h;
        if (exc < target && target <= inc) { selByte = (unsigned)tid; selExc = exc; }
        __syncthreads();
        prefix |= (selByte << shift);
        target -= selExc;
        below += selExc;
        __syncthreads();
    }
    const float Tval = __uint_as_float(prefix);
    const float Dv = Dsh;

    // ---- final: loss = sum_{v<T} relu(D-v) + (32-below)*relu(D-T) ----
    float part = 0.f;
    for (int i = tid; i < cnt; i += 256) {
        float v = cand[i];
        if (v < Tval) part += fmaxf(Dv - v, 0.f);
    }
#pragma unroll
    for (int o = 16; o; o >>= 1) part += __shfl_xor_sync(0xffffffffu, part, o);
    if (lane == 0) wpart[wid] = part;
    __syncthreads();
    if (tid == 0) {
        float loss = 0.f;
#pragma unroll
        for (int w = 0; w < 8; w++) loss += wpart[w];
        loss += (float)(KSEL - (int)below) * fmaxf(Dv - Tval, 0.f);
        g_rowLoss[row] = loss;
        __threadfence();
        ticket = atomicAdd(&g_done, 1u);
    }
    __syncthreads();

    // ---- last block: deterministic final reduction ----
    if (ticket == 2 * NA - 1) {
        float s = g_rowLoss[tid] + g_rowLoss[tid + 256] +
                  g_rowLoss[tid + 512] + g_rowLoss[tid + 768];
        sred[tid] = s;
        __syncthreads();
        for (int x = 128; x > 0; x >>= 1) {
            if (tid < x) sred[tid] += sred[tid + x];
            __syncthreads();
        }
        if (tid == 0) outp[0] = sred[0] / (float)(NA * KSEL);
    }
}

// ---------------------------------------------------------------------------
extern "C" void kernel_launch(void* const* d_in, const int* in_sizes, int n_in,
                              void* d_out, int out_size) {
    const float* out1 = (const float*)d_in[0];
    const float* out2 = (const float*)d_in[1];
    const int* an1 = (const int*)d_in[2];
    const int* an2 = (const int*)d_in[3];
    float* out = (float*)d_out;

    const int smem = (TA + TN) * SROW * (int)sizeof(float);  // 50688 B
    cudaFuncSetAttribute(k_dist, cudaFuncAttributeMaxDynamicSharedMemorySize, smem);

    dim3 g(NN / TN, NA / TA, 2);
    k_dist<<<g, 256, smem>>>(out1, out2, an1, an2);
    k_topk<<<2 * NA, 256>>>(out1, out2, an1, an2, out);
}